// round 12
// baseline (speedup 1.0000x reference)
#include <cuda_runtime.h>
#include <math.h>

// Problem constants
#define B  8
#define H  1024
#define W  1024
#define NTOT (B*H*W)

#define NT 256
#define TW 128         // tile width (output)
#define TH 8           // tile height (output)
#define SW 136         // shared row width in floats (128 + 4 halo each side)
#define NC 34          // float4 cells per shared row
#define SHI 16         // iter kernel shared rows (8 + 4 halo each side)
#define SHN 12         // init kernel shared rows (8 + 2 halo each side)

#define PINF  __int_as_float(0x7f800000)
#define NINF  __int_as_float(0xff800000)
#define FULLM 0xFFFFFFFFu

// ---------------------------------------------------------------------------
// Scratch (allocation-free)
// ---------------------------------------------------------------------------
__device__ float g_prob [NTOT];
__device__ float g_skelP[NTOT];
__device__ float g_skelT[NTOT];
__device__ float g_bufA [NTOT];
__device__ float g_bufB [NTOT];
__device__ double g_sums[7];   // 0:sp*t 1:sp 2:st*p 3:st 4:p*t 5:p 6:t

__global__ void zero_sums() { if (threadIdx.x < 7) g_sums[threadIdx.x] = 0.0; }

// ---------------------------------------------------------------------------
// Helpers
// ---------------------------------------------------------------------------
__device__ __forceinline__ float4 ld4(const float* p) { return *(const float4*)p; }
__device__ __forceinline__ void   st4(float* p, float4 v) { *(float4*)p = v; }

__device__ __forceinline__ float4 min4(float4 a, float4 b) {
    return make_float4(fminf(a.x,b.x), fminf(a.y,b.y), fminf(a.z,b.z), fminf(a.w,b.w));
}

__device__ __forceinline__ float4 horiz_min(float4 v, float4 c, float l, float r) {
    float4 m;
    m.x = fminf(v.x, fminf(l,   c.y));
    m.y = fminf(v.y, fminf(c.x, c.z));
    m.z = fminf(v.z, fminf(c.y, c.w));
    m.w = fminf(v.w, fminf(c.z, r  ));
    return m;
}

__device__ __forceinline__ float4 cross_min(float4 u, float4 c, float4 d, float l, float r) {
    return horiz_min(min4(min4(u, d), c), c, l, r);
}

__device__ __forceinline__ float4 row_max3(float4 c, float l, float r) {
    float4 m;
    m.x = fmaxf(l,   fmaxf(c.x, c.y));
    m.y = fmaxf(c.x, fmaxf(c.y, c.z));
    m.z = fmaxf(c.y, fmaxf(c.z, c.w));
    m.w = fmaxf(c.z, fmaxf(c.w, r  ));
    return m;
}

__device__ __forceinline__ float4 max4(float4 a, float4 b) {
    return make_float4(fmaxf(a.x,b.x), fmaxf(a.y,b.y), fmaxf(a.z,b.z), fmaxf(a.w,b.w));
}

__device__ __forceinline__ float4 dil3x3(const float* s, int o) {
    float4 m0 = row_max3(ld4(&s[o-SW]), s[o-SW-1], s[o-SW+4]);
    float4 m1 = row_max3(ld4(&s[o   ]), s[o   -1], s[o   +4]);
    float4 m2 = row_max3(ld4(&s[o+SW]), s[o+SW-1], s[o+SW+4]);
    return max4(max4(m0, m1), m2);
}

__device__ __forceinline__ void mask_oob(float4& v, int gy, int gx, float pad) {
    if ((unsigned)gy >= H) { v.x = v.y = v.z = v.w = pad; return; }
    if ((unsigned)(gx+0) >= W) v.x = pad;
    if ((unsigned)(gx+1) >= W) v.y = pad;
    if ((unsigned)(gx+2) >= W) v.z = pad;
    if ((unsigned)(gx+3) >= W) v.w = pad;
}

__device__ __forceinline__ void skel_update(float4& s, float4 e, float4 d) {
    float4 dl;
    dl.x = fmaxf(e.x - d.x, 0.f);
    dl.y = fmaxf(e.y - d.y, 0.f);
    dl.z = fmaxf(e.z - d.z, 0.f);
    dl.w = fmaxf(e.w - d.w, 0.f);
    s.x += fmaxf(dl.x - s.x*dl.x, 0.f);
    s.y += fmaxf(dl.y - s.y*dl.y, 0.f);
    s.z += fmaxf(dl.z - s.z*dl.z, 0.f);
    s.w += fmaxf(dl.w - s.w*dl.w, 0.f);
}

// ---------------------------------------------------------------------------
// Pair-blocked erode pass (smem -> smem), shuffle horizontal taps.
// Jobs: (p, c) with c in [0, NC); row = rbase + 2p. njobs multiple of NC.
// ---------------------------------------------------------------------------
__device__ __forceinline__ void erode_pair_pass(
    const float* __restrict__ src, float* __restrict__ dst,
    int rbase, int njobs, int tid)
{
    int j = (tid < njobs) ? tid : (njobs - 1);
    int p = j / NC, c = j - p * NC;
    int c4 = c * 4;
    int o = (rbase + 2*p)*SW + c4;

    float4 up = ld4(&src[o - SW]);
    float4 ca = ld4(&src[o]);
    float4 cb = ld4(&src[o + SW]);
    float4 dn = ld4(&src[o + 2*SW]);

    float l_a = __shfl_up_sync  (FULLM, ca.w, 1);
    float r_a = __shfl_down_sync(FULLM, ca.x, 1);
    float l_b = __shfl_up_sync  (FULLM, cb.w, 1);
    float r_b = __shfl_down_sync(FULLM, cb.x, 1);

    int lane = tid & 31;
    if (c == 0 || lane == 0)        { l_a = src[o-1];    l_b = src[o+SW-1]; }
    if (c == NC-1 || lane == 31)    { r_a = src[o+4];    r_b = src[o+SW+4]; }

    if (tid < njobs) {
        float4 q  = min4(ca, cb);
        float4 ea = horiz_min(min4(up, q), ca, l_a, r_a);
        float4 eb = horiz_min(min4(q, dn), cb, l_b, r_b);
        st4(&dst[o],      ea);
        st4(&dst[o + SW], eb);
    }
}

// ---------------------------------------------------------------------------
// INTERIOR fused double iteration (no masking; t1 == e2 == s2):
//   s1 = erode(img) directly from global; s2 = erode(s1); s3 = erode(s2)
//   d1 = dilate(s2) vs s1;  d2 = dilate(s3) vs s2;  imgOut = s2
// Buffers: sB (s1), sC (s2), sA (s3). 4 phases.
// Final pass: lane-consecutive cells -> conflict-free LDS.
// ---------------------------------------------------------------------------
template<bool WRITE_IMG>
__device__ __forceinline__ void iter2_interior(
    const float* __restrict__ img, float* __restrict__ imgOut,
    float* __restrict__ skel, int x0, int y0,
    float* sA, float* sB, float* sC, int tid)
{
    // ---- phase 1: s1 = erode(img) from global, rows 1..14 (7 pairs x 34 = 238)
    {
        int j = (tid < 238) ? tid : 237;
        int p = j / NC, c = j - p * NC;
        int c4 = c * 4;
        int row = 1 + 2*p;
        int gy = y0 - 4 + row;
        int gx = x0 - 4 + c4;
        const float* g0 = &img[(size_t)(gy-1) * W + gx];

        float4 up = ld4(g0);
        float4 ca = ld4(g0 + W);
        float4 cb = ld4(g0 + 2*W);
        float4 dn = ld4(g0 + 3*W);

        float l_a = __shfl_up_sync  (FULLM, ca.w, 1);
        float r_a = __shfl_down_sync(FULLM, ca.x, 1);
        float l_b = __shfl_up_sync  (FULLM, cb.w, 1);
        float r_b = __shfl_down_sync(FULLM, cb.x, 1);

        int lane = tid & 31;
        if (c == 0 || lane == 0)     { l_a = g0[W - 1];   l_b = g0[2*W - 1]; }
        if (c == NC-1 || lane == 31) { r_a = g0[W + 4];   r_b = g0[2*W + 4]; }

        if (tid < 238) {
            int o = row*SW + c4;
            float4 q  = min4(ca, cb);
            float4 ea = horiz_min(min4(up, q), ca, l_a, r_a);
            float4 eb = horiz_min(min4(q, dn), cb, l_b, r_b);
            st4(&sB[o],      ea);
            st4(&sB[o + SW], eb);
        }
    }
    __syncthreads();

    erode_pair_pass(sB, sC, 2, 204, tid);   // s2: rows 2..13 (6 pairs)
    __syncthreads();
    erode_pair_pass(sC, sA, 3, 170, tid);   // s3: rows 3..12 (5 pairs)
    __syncthreads();

    // ---- final: rows 4..11, 4 pairs x 32 cells; lane = cell-1 (16B stride)
    if (tid < 128) {
        int p = tid >> 5;
        int c4 = ((tid & 31) + 1) * 4;
        int ra = 4 + 2*p;
        int o = ra*SW + c4;

        // d1 over s2 (sC): rows ra-1 .. ra+2
        float4 h0 = row_max3(ld4(&sC[o-SW]),   sC[o-SW-1],   sC[o-SW+4]);
        float4 va = ld4(&sC[o]);
        float4 h1 = row_max3(va,               sC[o-1],      sC[o+4]);
        float4 vb = ld4(&sC[o+SW]);
        float4 h2 = row_max3(vb,               sC[o+SW-1],   sC[o+SW+4]);
        float4 h3 = row_max3(ld4(&sC[o+2*SW]), sC[o+2*SW-1], sC[o+2*SW+4]);
        float4 hq = max4(h1, h2);
        float4 d1a = max4(h0, hq);
        float4 d1b = max4(hq, h3);

        float4 e1a = ld4(&sB[o]);
        float4 e1b = ld4(&sB[o + SW]);

        size_t idx = (size_t)(y0 + ra - 4) * W + (x0 + c4 - 4);
        float4 s  = ld4(&skel[idx]);
        float4 s2 = ld4(&skel[idx + W]);
        skel_update(s,  e1a, d1a);
        skel_update(s2, e1b, d1b);

        // d2 over s3 (sA)
        float4 g0 = row_max3(ld4(&sA[o-SW]),   sA[o-SW-1],   sA[o-SW+4]);
        float4 g1 = row_max3(ld4(&sA[o]),      sA[o-1],      sA[o+4]);
        float4 g2 = row_max3(ld4(&sA[o+SW]),   sA[o+SW-1],   sA[o+SW+4]);
        float4 g3 = row_max3(ld4(&sA[o+2*SW]), sA[o+2*SW-1], sA[o+2*SW+4]);
        float4 gq = max4(g1, g2);
        float4 d2a = max4(g0, gq);
        float4 d2b = max4(gq, g3);

        skel_update(s,  va, d2a);
        skel_update(s2, vb, d2b);

        if (WRITE_IMG) { st4(&imgOut[idx], va); st4(&imgOut[idx + W], vb); }
        st4(&skel[idx],     s);
        st4(&skel[idx + W], s2);
    }
}

// ---------------------------------------------------------------------------
// BORDER fused double iteration, 3-buffer masked variant.
//   sA: img -> t1 -> t2     sB: e1     sC: e2
// ---------------------------------------------------------------------------
template<bool WRITE_IMG>
__device__ __forceinline__ void iter2_border(
    const float* __restrict__ img, float* __restrict__ imgOut,
    float* __restrict__ skel, int x0, int y0,
    float* sA, float* sB, float* sC, int tid)
{
    // load img rows 0..15, OOB +inf
    for (int i = tid; i < SHI*NC; i += NT) {
        int r = i / NC, c4 = (i - r*NC) * 4;
        int gy = y0 - 4 + r, gx = x0 - 4 + c4;
        float4 v = make_float4(PINF, PINF, PINF, PINF);
        if ((unsigned)gy < H) {
            const float* row = &img[gy*W];
            if ((unsigned)(gx+0) < W) v.x = row[gx+0];
            if ((unsigned)(gx+1) < W) v.y = row[gx+1];
            if ((unsigned)(gx+2) < W) v.z = row[gx+2];
            if ((unsigned)(gx+3) < W) v.w = row[gx+3];
        }
        st4(&sA[r*SW + c4], v);
    }
    __syncthreads();

    // e1 = erode(img), rows 1..14, masked +inf
    for (int i = tid; i < 14*NC; i += NT) {
        int r = 1 + i / NC, c4 = (i % NC) * 4;
        int o = r*SW + c4;
        float4 e = cross_min(ld4(&sA[o-SW]), ld4(&sA[o]), ld4(&sA[o+SW]),
                             sA[o-1], sA[o+4]);
        mask_oob(e, y0-4+r, x0-4+c4, PINF);
        st4(&sB[o], e);
    }
    __syncthreads();

    // t1 (masked -inf) -> sA ; e2 (masked +inf) -> sC ; rows 2..13
    for (int i = tid; i < 12*NC; i += NT) {
        int r = 2 + i / NC, c4 = (i % NC) * 4;
        int o = r*SW + c4;
        float4 t = cross_min(ld4(&sB[o-SW]), ld4(&sB[o]), ld4(&sB[o+SW]),
                             sB[o-1], sB[o+4]);
        float4 e2 = t;
        mask_oob(t,  y0-4+r, x0-4+c4, NINF);
        mask_oob(e2, y0-4+r, x0-4+c4, PINF);
        st4(&sA[o], t);
        st4(&sC[o], e2);
    }
    __syncthreads();

    int r  = 4 + (tid >> 5);
    int c4 = ((tid & 31) + 1) * 4;
    int o  = r*SW + c4;
    size_t idx = (size_t)(y0 + r - 4) * W + (x0 + c4 - 4);
    float4 s;
    if (tid < 128) {
        float4 d1 = dil3x3(sA, o);
        float4 e1 = ld4(&sB[o]);
        s = ld4(&skel[idx]);
        skel_update(s, e1, d1);
    }
    __syncthreads();

    // t2 = erode(e2) masked -inf -> sA, rows 3..12
    for (int i = tid; i < 10*NC; i += NT) {
        int rr = 3 + i / NC, cc = (i % NC) * 4;
        int oo = rr*SW + cc;
        float4 t = cross_min(ld4(&sC[oo-SW]), ld4(&sC[oo]), ld4(&sC[oo+SW]),
                             sC[oo-1], sC[oo+4]);
        mask_oob(t, y0-4+rr, x0-4+cc, NINF);
        st4(&sA[oo], t);
    }
    __syncthreads();

    if (tid < 128) {
        float4 d2 = dil3x3(sA, o);
        float4 e2 = ld4(&sC[o]);
        skel_update(s, e2, d2);
        if (WRITE_IMG) st4(&imgOut[idx], e2);
        st4(&skel[idx], s);
    }
}

template<bool WRITE_IMG>
__global__ __launch_bounds__(NT)
void iter2_kernel(const float* __restrict__ imgIn, float* __restrict__ imgOut,
                  float* __restrict__ skel)
{
    __shared__ float sA[SHI*SW];
    __shared__ float sB[SHI*SW];
    __shared__ float sC[SHI*SW];
    int x0 = blockIdx.x * TW, y0 = blockIdx.y * TH;
    size_t off = (size_t)blockIdx.z * H * W;
    int tid = threadIdx.x;
    bool border = (blockIdx.x == 0) | (blockIdx.x == gridDim.x-1) |
                  (blockIdx.y == 0) | (blockIdx.y == gridDim.y-1);
    if (border) iter2_border<WRITE_IMG>(imgIn+off, imgOut+off, skel+off, x0, y0, sA, sB, sC, tid);
    else        iter2_interior<WRITE_IMG>(imgIn+off, imgOut+off, skel+off, x0, y0, sA, sB, sC, tid);
}

// ---------------------------------------------------------------------------
// Init: base = sigmoid(pred) | float(target)
//   e = erode(base) (masked -inf); d = dilate3x3(e); skel0 = relu(base-d)
// 128x8 tile, halo 2: shared rows 0..11.
// ---------------------------------------------------------------------------
template<bool IS_PRED, bool BORDER>
__device__ __forceinline__ void init_impl(
    const float* __restrict__ pred, const int* __restrict__ targ,
    float* __restrict__ baseOut, float* __restrict__ skelOut,
    int x0, int y0, float* s0, float* s1, int tid)
{
    for (int i = tid; i < SHN*NC; i += NT) {
        int r = i / NC, c4 = (i - r*NC) * 4;
        int gy = y0 - 2 + r, gx = x0 - 4 + c4;
        float4 v;
        if (!BORDER) {
            if (IS_PRED) {
                float4 x = ld4(&pred[gy*W + gx]);
                v.x = 1.f / (1.f + __expf(-x.x));
                v.y = 1.f / (1.f + __expf(-x.y));
                v.z = 1.f / (1.f + __expf(-x.z));
                v.w = 1.f / (1.f + __expf(-x.w));
            } else {
                int4 t = *(const int4*)&targ[gy*W + gx];
                v = make_float4((float)t.x, (float)t.y, (float)t.z, (float)t.w);
            }
        } else {
            v = make_float4(PINF, PINF, PINF, PINF);
            if ((unsigned)gy < H) {
                #pragma unroll
                for (int k = 0; k < 4; k++) {
                    float* vk = k==0 ? &v.x : k==1 ? &v.y : k==2 ? &v.z : &v.w;
                    if ((unsigned)(gx+k) < W) {
                        if (IS_PRED) { float x = pred[gy*W + gx + k]; *vk = 1.f/(1.f+__expf(-x)); }
                        else         { *vk = (float)targ[gy*W + gx + k]; }
                    }
                }
            }
        }
        st4(&s0[r*SW + c4], v);
    }
    __syncthreads();

    // e = erode(base), rows 1..10; masked -inf (feeds dilate)
    for (int i = tid; i < 10*NC; i += NT) {
        int r = 1 + i / NC, c4 = (i % NC) * 4;
        int o = r*SW + c4;
        float4 e = cross_min(ld4(&s0[o-SW]), ld4(&s0[o]), ld4(&s0[o+SW]),
                             s0[o-1], s0[o+4]);
        if (BORDER) mask_oob(e, y0-2+r, x0-4+c4, NINF);
        st4(&s1[o], e);
    }
    __syncthreads();

    // final: rows 2..9, one row per thread; lane-consecutive cells
    {
        int r  = 2 + (tid >> 5);
        int c4 = ((tid & 31) + 1) * 4;
        int o  = r*SW + c4;
        float4 d = dil3x3(s1, o);
        float4 base = ld4(&s0[o]);
        float4 sk;
        sk.x = fmaxf(base.x - d.x, 0.f);
        sk.y = fmaxf(base.y - d.y, 0.f);
        sk.z = fmaxf(base.z - d.z, 0.f);
        sk.w = fmaxf(base.w - d.w, 0.f);
        size_t idx = (size_t)(y0 + r - 2) * W + (x0 + c4 - 4);
        st4(&baseOut[idx], base);
        st4(&skelOut[idx], sk);
    }
}

template<bool IS_PRED>
__global__ __launch_bounds__(NT)
void init_kernel(const float* __restrict__ pred, const int* __restrict__ targ,
                 float* __restrict__ baseOut, float* __restrict__ skelOut)
{
    __shared__ float s0[SHN*SW];
    __shared__ float s1[SHN*SW];
    int x0 = blockIdx.x * TW, y0 = blockIdx.y * TH;
    size_t off = (size_t)blockIdx.z * H * W;
    int tid = threadIdx.x;
    const float* p = IS_PRED ? pred + off : nullptr;
    const int*   t = IS_PRED ? nullptr : targ + off;
    bool border = (blockIdx.x == 0) | (blockIdx.x == gridDim.x-1) |
                  (blockIdx.y == 0) | (blockIdx.y == gridDim.y-1);
    if (border) init_impl<IS_PRED, true >(p, t, baseOut+off, skelOut+off, x0, y0, s0, s1, tid);
    else        init_impl<IS_PRED, false>(p, t, baseOut+off, skelOut+off, x0, y0, s0, s1, tid);
}

// ---------------------------------------------------------------------------
// Reduction: 7 sums over 8M elements
// ---------------------------------------------------------------------------
#define RED_BLOCKS 2048
#define RED_THREADS 256

__global__ __launch_bounds__(RED_THREADS)
void reduce_kernel(const int* __restrict__ targ)
{
    const int NV = NTOT / 4;
    const float4* p4   = (const float4*)g_prob;
    const float4* sp4  = (const float4*)g_skelP;
    const float4* st4p = (const float4*)g_skelT;
    const int4*   t4   = (const int4*)targ;

    float a0=0.f, a1=0.f, a2=0.f, a3=0.f, a4=0.f, a5=0.f, a6=0.f;

    for (int v = blockIdx.x * RED_THREADS + threadIdx.x; v < NV;
         v += gridDim.x * RED_THREADS) {
        float4 p  = p4[v];
        float4 sp = sp4[v];
        float4 st = st4p[v];
        int4   ti = t4[v];
        float tx = (float)ti.x, ty = (float)ti.y, tz = (float)ti.z, tw = (float)ti.w;

        a0 += sp.x*tx + sp.y*ty + sp.z*tz + sp.w*tw;
        a1 += sp.x + sp.y + sp.z + sp.w;
        a2 += st.x*p.x + st.y*p.y + st.z*p.z + st.w*p.w;
        a3 += st.x + st.y + st.z + st.w;
        a4 += p.x*tx + p.y*ty + p.z*tz + p.w*tw;
        a5 += p.x + p.y + p.z + p.w;
        a6 += tx + ty + tz + tw;
    }

    #pragma unroll
    for (int off = 16; off > 0; off >>= 1) {
        a0 += __shfl_down_sync(0xFFFFFFFF, a0, off);
        a1 += __shfl_down_sync(0xFFFFFFFF, a1, off);
        a2 += __shfl_down_sync(0xFFFFFFFF, a2, off);
        a3 += __shfl_down_sync(0xFFFFFFFF, a3, off);
        a4 += __shfl_down_sync(0xFFFFFFFF, a4, off);
        a5 += __shfl_down_sync(0xFFFFFFFF, a5, off);
        a6 += __shfl_down_sync(0xFFFFFFFF, a6, off);
    }

    __shared__ double sacc[7][RED_THREADS/32];
    int warp = threadIdx.x >> 5, lane = threadIdx.x & 31;
    if (lane == 0) {
        sacc[0][warp]=a0; sacc[1][warp]=a1; sacc[2][warp]=a2;
        sacc[3][warp]=a3; sacc[4][warp]=a4; sacc[5][warp]=a5; sacc[6][warp]=a6;
    }
    __syncthreads();
    if (threadIdx.x < 7) {
        double s = 0.0;
        #pragma unroll
        for (int wv = 0; wv < RED_THREADS/32; wv++) s += sacc[threadIdx.x][wv];
        atomicAdd(&g_sums[threadIdx.x], s);
    }
}

__global__ void finalize_kernel(float* __restrict__ out)
{
    double S_spt=g_sums[0], S_sp=g_sums[1], S_stp=g_sums[2], S_st=g_sums[3];
    double S_pt =g_sums[4], S_p =g_sums[5], S_t =g_sums[6];
    const double SMOOTH = 1.0;
    double tprec = (S_spt + SMOOTH) / (S_sp + SMOOTH);
    double tsens = (S_stp + SMOOTH) / (S_st + SMOOTH);
    double cl    = 2.0 * tprec * tsens / (tprec + tsens + 1e-7);
    double dice  = (2.0 * S_pt + SMOOTH) / (S_p + S_t + SMOOTH);
    out[0] = (float)(1.0 - (0.5 * dice + 0.5 * cl));
}

// ---------------------------------------------------------------------------
// Launch
// ---------------------------------------------------------------------------
extern "C" void kernel_launch(void* const* d_in, const int* in_sizes, int n_in,
                              void* d_out, int out_size)
{
    const float* pred = (const float*)d_in[0];
    const int*   targ = (const int*)d_in[1];
    float* out = (float*)d_out;

    float *prob, *skelP, *skelT, *bufA, *bufB;
    cudaGetSymbolAddress((void**)&prob,  g_prob);
    cudaGetSymbolAddress((void**)&skelP, g_skelP);
    cudaGetSymbolAddress((void**)&skelT, g_skelT);
    cudaGetSymbolAddress((void**)&bufA,  g_bufA);
    cudaGetSymbolAddress((void**)&bufB,  g_bufB);

    dim3 grd(W / TW, H / TH, B);   // 8 x 128 x 8

    zero_sums<<<1, 32>>>();

    // ---- pred skeleton: init + 5 fused double-iterations ----
    init_kernel<true><<<grd, NT>>>(pred, nullptr, prob, skelP);
    {
        const float* in = prob;
        float* ob = bufB;
        for (int i = 0; i < 5; i++) {
            if (i < 4) iter2_kernel<true ><<<grd, NT>>>(in, ob, skelP);
            else       iter2_kernel<false><<<grd, NT>>>(in, ob, skelP);
            in = ob;
            ob = (ob == bufB) ? bufA : bufB;
        }
    }

    // ---- target skeleton ----
    init_kernel<false><<<grd, NT>>>(nullptr, targ, bufA, skelT);
    {
        const float* in = bufA;
        float* ob = bufB;
        for (int i = 0; i < 5; i++) {
            if (i < 4) iter2_kernel<true ><<<grd, NT>>>(in, ob, skelT);
            else       iter2_kernel<false><<<grd, NT>>>(in, ob, skelT);
            in = ob;
            ob = (ob == bufB) ? bufA : bufB;
        }
    }

    reduce_kernel<<<RED_BLOCKS, RED_THREADS>>>(targ);
    finalize_kernel<<<1, 1>>>(out);
}

// round 15
// speedup vs baseline: 1.0517x; 1.0517x over previous
#include <cuda_runtime.h>
#include <math.h>

// Problem constants
#define B  8
#define H  1024
#define W  1024
#define NTOT (B*H*W)

#define NT 256
#define TW 64          // tile width (output)
#define TH 16          // tile height (output)
#define SW 72          // shared row width in floats (64 + 4 halo each side)
#define SH2I 24        // iter kernel shared rows: 16 + 4 halo each side
#define SHN 20         // init kernel shared rows: 16 + 2 halo each side

#define PINF  __int_as_float(0x7f800000)
#define NINF  __int_as_float(0xff800000)
#define FULLM 0xFFFFFFFFu

// ---------------------------------------------------------------------------
// Scratch (allocation-free)
// ---------------------------------------------------------------------------
__device__ float g_prob [NTOT];
__device__ float g_skelP[NTOT];
__device__ float g_skelT[NTOT];
__device__ float g_bufA [NTOT];
__device__ float g_bufB [NTOT];
__device__ double g_sums[7];   // 0:sp*t 1:sp 2:st*p 3:st 4:p*t 5:p 6:t

__global__ void zero_sums() { if (threadIdx.x < 7) g_sums[threadIdx.x] = 0.0; }

// ---------------------------------------------------------------------------
// Helpers
// ---------------------------------------------------------------------------
__device__ __forceinline__ float4 ld4(const float* p) { return *(const float4*)p; }
__device__ __forceinline__ void   st4(float* p, float4 v) { *(float4*)p = v; }

__device__ __forceinline__ float4 min4(float4 a, float4 b) {
    return make_float4(fminf(a.x,b.x), fminf(a.y,b.y), fminf(a.z,b.z), fminf(a.w,b.w));
}

__device__ __forceinline__ float4 horiz_min(float4 v, float4 c, float l, float r) {
    float4 m;
    m.x = fminf(v.x, fminf(l,   c.y));
    m.y = fminf(v.y, fminf(c.x, c.z));
    m.z = fminf(v.z, fminf(c.y, c.w));
    m.w = fminf(v.w, fminf(c.z, r  ));
    return m;
}

__device__ __forceinline__ float4 cross_min(float4 u, float4 c, float4 d, float l, float r) {
    return horiz_min(min4(min4(u, d), c), c, l, r);
}

__device__ __forceinline__ float4 row_max3(float4 c, float l, float r) {
    float4 m;
    m.x = fmaxf(l,   fmaxf(c.x, c.y));
    m.y = fmaxf(c.x, fmaxf(c.y, c.z));
    m.z = fmaxf(c.y, fmaxf(c.z, c.w));
    m.w = fmaxf(c.z, fmaxf(c.w, r  ));
    return m;
}

__device__ __forceinline__ float4 max4(float4 a, float4 b) {
    return make_float4(fmaxf(a.x,b.x), fmaxf(a.y,b.y), fmaxf(a.z,b.z), fmaxf(a.w,b.w));
}

// horizontal max3 of one shared row with shuffle taps (smem fallback on lb/rb)
__device__ __forceinline__ float4 hrow3(const float* s, int o, bool lb, bool rb) {
    float4 c = ld4(&s[o]);
    float l = __shfl_up_sync  (FULLM, c.w, 1);
    float r = __shfl_down_sync(FULLM, c.x, 1);
    if (lb) l = s[o-1];
    if (rb) r = s[o+4];
    return row_max3(c, l, r);
}
// same but also returns the center row
__device__ __forceinline__ float4 hrow3_keep(const float* s, int o, bool lb, bool rb, float4& c) {
    c = ld4(&s[o]);
    float l = __shfl_up_sync  (FULLM, c.w, 1);
    float r = __shfl_down_sync(FULLM, c.x, 1);
    if (lb) l = s[o-1];
    if (rb) r = s[o+4];
    return row_max3(c, l, r);
}

__device__ __forceinline__ float4 dil3x3(const float* s, int o) {
    float4 m0 = row_max3(ld4(&s[o-SW]), s[o-SW-1], s[o-SW+4]);
    float4 m1 = row_max3(ld4(&s[o   ]), s[o   -1], s[o   +4]);
    float4 m2 = row_max3(ld4(&s[o+SW]), s[o+SW-1], s[o+SW+4]);
    return max4(max4(m0, m1), m2);
}

__device__ __forceinline__ void mask_oob(float4& v, int gy, int gx, float pad) {
    if ((unsigned)gy >= H) { v.x = v.y = v.z = v.w = pad; return; }
    if ((unsigned)(gx+0) >= W) v.x = pad;
    if ((unsigned)(gx+1) >= W) v.y = pad;
    if ((unsigned)(gx+2) >= W) v.z = pad;
    if ((unsigned)(gx+3) >= W) v.w = pad;
}

__device__ __forceinline__ void skel_update(float4& s, float4 e, float4 d) {
    float4 dl;
    dl.x = fmaxf(e.x - d.x, 0.f);
    dl.y = fmaxf(e.y - d.y, 0.f);
    dl.z = fmaxf(e.z - d.z, 0.f);
    dl.w = fmaxf(e.w - d.w, 0.f);
    s.x += fmaxf(dl.x - s.x*dl.x, 0.f);
    s.y += fmaxf(dl.y - s.y*dl.y, 0.f);
    s.z += fmaxf(dl.z - s.z*dl.z, 0.f);
    s.w += fmaxf(dl.w - s.w*dl.w, 0.f);
}

// ---------------------------------------------------------------------------
// Pair-blocked erode pass (smem -> smem), shuffle horizontal taps.
// njobs multiple of 18.
// ---------------------------------------------------------------------------
__device__ __forceinline__ void erode_pair_pass(
    const float* __restrict__ src, float* __restrict__ dst,
    int rbase, int njobs, int tid)
{
    int j = (tid < njobs) ? tid : (njobs - 1);
    int p = j / 18, c = j - p * 18;
    int c4 = c * 4;
    int o = (rbase + 2*p)*SW + c4;

    float4 up = ld4(&src[o - SW]);
    float4 ca = ld4(&src[o]);
    float4 cb = ld4(&src[o + SW]);
    float4 dn = ld4(&src[o + 2*SW]);

    float l_a = __shfl_up_sync  (FULLM, ca.w, 1);
    float r_a = __shfl_down_sync(FULLM, ca.x, 1);
    float l_b = __shfl_up_sync  (FULLM, cb.w, 1);
    float r_b = __shfl_down_sync(FULLM, cb.x, 1);

    int lane = tid & 31;
    if (c == 0 || lane == 0)   { l_a = src[o-1];    l_b = src[o+SW-1]; }
    if (c == 17 || lane == 31) { r_a = src[o+4];    r_b = src[o+SW+4]; }

    if (tid < njobs) {
        float4 q  = min4(ca, cb);
        float4 ea = horiz_min(min4(up, q), ca, l_a, r_a);
        float4 eb = horiz_min(min4(q, dn), cb, l_b, r_b);
        st4(&dst[o],      ea);
        st4(&dst[o + SW], eb);
    }
}

// ---------------------------------------------------------------------------
// INTERIOR fused double iteration (no masking; t1 == e2 == s2):
//   s1 = erode(img) directly from global; s2 = erode(s1); s3 = erode(s2)
//   d1 = dilate(s2) vs s1;  d2 = dilate(s3) vs s2;  imgOut = s2
// Buffers: sB (s1), sC (s2), sA (s3). 4 phases.
// Final pass: shuffle-based dilate taps, sequenced for low registers.
// ---------------------------------------------------------------------------
template<bool WRITE_IMG>
__device__ __forceinline__ void iter2_interior(
    const float* __restrict__ img, float* __restrict__ imgOut,
    float* __restrict__ skel, int x0, int y0,
    float* sA, float* sB, float* sC, int tid)
{
    // ---- phase 1: s1 = erode(img) from global, rows 1..22 (11 pairs x 18)
    {
        int j = (tid < 198) ? tid : 197;
        int p = j / 18, c = j - p * 18;
        int c4 = c * 4;
        int row = 1 + 2*p;
        int gy = y0 - 4 + row;
        int gx = x0 - 4 + c4;
        const float* g0 = &img[(size_t)(gy-1) * W + gx];

        float4 up = ld4(g0);
        float4 ca = ld4(g0 + W);
        float4 cb = ld4(g0 + 2*W);
        float4 dn = ld4(g0 + 3*W);

        float l_a = __shfl_up_sync  (FULLM, ca.w, 1);
        float r_a = __shfl_down_sync(FULLM, ca.x, 1);
        float l_b = __shfl_up_sync  (FULLM, cb.w, 1);
        float r_b = __shfl_down_sync(FULLM, cb.x, 1);

        int lane = tid & 31;
        if (c == 0 || lane == 0)   { l_a = g0[W - 1];   l_b = g0[2*W - 1]; }
        if (c == 17 || lane == 31) { r_a = g0[W + 4];   r_b = g0[2*W + 4]; }

        if (tid < 198) {
            int o = row*SW + c4;
            float4 q  = min4(ca, cb);
            float4 ea = horiz_min(min4(up, q), ca, l_a, r_a);
            float4 eb = horiz_min(min4(q, dn), cb, l_b, r_b);
            st4(&sB[o],      ea);
            st4(&sB[o + SW], eb);
        }
    }
    __syncthreads();

    erode_pair_pass(sB, sC, 2, 180, tid);   // s2: rows 2..21
    __syncthreads();
    erode_pair_pass(sC, sA, 3, 162, tid);   // s3: rows 3..20
    __syncthreads();

    // ---- final: rows 4..19, 8 pairs x 16 cells; shuffle dilate taps
    if (tid < 128) {
        int p = tid >> 4, c4 = ((tid & 15) + 1) * 4;
        int ra = 4 + 2*p;
        int o = ra*SW + c4;
        bool lb = (tid & 15) == 0;
        bool rb = (tid & 15) == 15;

        size_t idx = (size_t)(y0 + ra - 4) * W + (x0 + c4 - 4);
        float4 s  = ld4(&skel[idx]);
        float4 s2 = ld4(&skel[idx + W]);

        // ---- d1 over s2 (sC), rows ra-1..ra+2; consume immediately
        float4 va, vb;
        {
            float4 h0 = hrow3(sC, o - SW, lb, rb);
            float4 h1 = hrow3_keep(sC, o, lb, rb, va);
            float4 h2 = hrow3_keep(sC, o + SW, lb, rb, vb);
            float4 h3 = hrow3(sC, o + 2*SW, lb, rb);
            float4 hq  = max4(h1, h2);
            float4 d1a = max4(h0, hq);
            float4 d1b = max4(hq, h3);
            float4 e1a = ld4(&sB[o]);
            float4 e1b = ld4(&sB[o + SW]);
            skel_update(s,  e1a, d1a);
            skel_update(s2, e1b, d1b);
        }

        // ---- d2 over s3 (sA), rows ra-1..ra+2
        {
            float4 g0 = hrow3(sA, o - SW, lb, rb);
            float4 g1 = hrow3(sA, o, lb, rb);
            float4 g2 = hrow3(sA, o + SW, lb, rb);
            float4 g3 = hrow3(sA, o + 2*SW, lb, rb);
            float4 gq  = max4(g1, g2);
            float4 d2a = max4(g0, gq);
            float4 d2b = max4(gq, g3);
            skel_update(s,  va, d2a);
            skel_update(s2, vb, d2b);
        }

        if (WRITE_IMG) { st4(&imgOut[idx], va); st4(&imgOut[idx + W], vb); }
        st4(&skel[idx],     s);
        st4(&skel[idx + W], s2);
    }
}

// ---------------------------------------------------------------------------
// BORDER fused double iteration, 3-buffer masked variant (R11 path).
// ---------------------------------------------------------------------------
template<bool WRITE_IMG>
__device__ __forceinline__ void iter2_border(
    const float* __restrict__ img, float* __restrict__ imgOut,
    float* __restrict__ skel, int x0, int y0,
    float* sA, float* sB, float* sC, int tid)
{
    for (int i = tid; i < SH2I*18; i += NT) {
        int r = i / 18, c4 = (i - r*18) * 4;
        int gy = y0 - 4 + r, gx = x0 - 4 + c4;
        float4 v = make_float4(PINF, PINF, PINF, PINF);
        if ((unsigned)gy < H) {
            const float* row = &img[gy*W];
            if ((unsigned)(gx+0) < W) v.x = row[gx+0];
            if ((unsigned)(gx+1) < W) v.y = row[gx+1];
            if ((unsigned)(gx+2) < W) v.z = row[gx+2];
            if ((unsigned)(gx+3) < W) v.w = row[gx+3];
        }
        st4(&sA[r*SW + c4], v);
    }
    __syncthreads();

    for (int i = tid; i < 22*18; i += NT) {
        int r = 1 + i / 18, c4 = (i % 18) * 4;
        int o = r*SW + c4;
        float4 e = cross_min(ld4(&sA[o-SW]), ld4(&sA[o]), ld4(&sA[o+SW]),
                             sA[o-1], sA[o+4]);
        mask_oob(e, y0-4+r, x0-4+c4, PINF);
        st4(&sB[o], e);
    }
    __syncthreads();

    for (int i = tid; i < 20*18; i += NT) {
        int r = 2 + i / 18, c4 = (i % 18) * 4;
        int o = r*SW + c4;
        float4 t = cross_min(ld4(&sB[o-SW]), ld4(&sB[o]), ld4(&sB[o+SW]),
                             sB[o-1], sB[o+4]);
        float4 e2 = t;
        mask_oob(t,  y0-4+r, x0-4+c4, NINF);
        mask_oob(e2, y0-4+r, x0-4+c4, PINF);
        st4(&sA[o], t);
        st4(&sC[o], e2);
    }
    __syncthreads();

    int r  = 4 + (tid >> 4);
    int c4 = ((tid & 15) + 1) * 4;
    int o  = r*SW + c4;
    size_t idx = (size_t)(y0 + r - 4) * W + (x0 + c4 - 4);
    float4 s;
    if (tid < 128) {
        float4 d1 = dil3x3(sA, o);
        float4 e1 = ld4(&sB[o]);
        s = ld4(&skel[idx]);
        skel_update(s, e1, d1);
    }
    __syncthreads();

    for (int i = tid; i < 18*18; i += NT) {
        int rr = 3 + i / 18, cc = (i % 18) * 4;
        int oo = rr*SW + cc;
        float4 t = cross_min(ld4(&sC[oo-SW]), ld4(&sC[oo]), ld4(&sC[oo+SW]),
                             sC[oo-1], sC[oo+4]);
        mask_oob(t, y0-4+rr, x0-4+cc, NINF);
        st4(&sA[oo], t);
    }
    __syncthreads();

    if (tid < 128) {
        float4 d2 = dil3x3(sA, o);
        float4 e2 = ld4(&sC[o]);
        skel_update(s, e2, d2);
        if (WRITE_IMG) st4(&imgOut[idx], e2);
        st4(&skel[idx], s);
    }
}

template<bool WRITE_IMG>
__global__ __launch_bounds__(NT)
void iter2_kernel(const float* __restrict__ imgIn, float* __restrict__ imgOut,
                  float* __restrict__ skel)
{
    __shared__ float sA[SH2I*SW];
    __shared__ float sB[SH2I*SW];
    __shared__ float sC[SH2I*SW];
    int x0 = blockIdx.x * TW, y0 = blockIdx.y * TH;
    size_t off = (size_t)blockIdx.z * H * W;
    int tid = threadIdx.x;
    bool border = (blockIdx.x == 0) | (blockIdx.x == gridDim.x-1) |
                  (blockIdx.y == 0) | (blockIdx.y == gridDim.y-1);
    if (border) iter2_border<WRITE_IMG>(imgIn+off, imgOut+off, skel+off, x0, y0, sA, sB, sC, tid);
    else        iter2_interior<WRITE_IMG>(imgIn+off, imgOut+off, skel+off, x0, y0, sA, sB, sC, tid);
}

// ---------------------------------------------------------------------------
// Init: base = sigmoid(pred) | float(target)
// ---------------------------------------------------------------------------
template<bool IS_PRED, bool BORDER>
__device__ __forceinline__ void init_impl(
    const float* __restrict__ pred, const int* __restrict__ targ,
    float* __restrict__ baseOut, float* __restrict__ skelOut,
    int x0, int y0, float* s0, float* s1, int tid)
{
    for (int i = tid; i < SHN*18; i += NT) {
        int r = i / 18, c4 = (i - r*18) * 4;
        int gy = y0 - 2 + r, gx = x0 - 4 + c4;
        float4 v;
        if (!BORDER) {
            if (IS_PRED) {
                float4 x = ld4(&pred[gy*W + gx]);
                v.x = 1.f / (1.f + __expf(-x.x));
                v.y = 1.f / (1.f + __expf(-x.y));
                v.z = 1.f / (1.f + __expf(-x.z));
                v.w = 1.f / (1.f + __expf(-x.w));
            } else {
                int4 t = *(const int4*)&targ[gy*W + gx];
                v = make_float4((float)t.x, (float)t.y, (float)t.z, (float)t.w);
            }
        } else {
            v = make_float4(PINF, PINF, PINF, PINF);
            if ((unsigned)gy < H) {
                #pragma unroll
                for (int k = 0; k < 4; k++) {
                    float* vk = k==0 ? &v.x : k==1 ? &v.y : k==2 ? &v.z : &v.w;
                    if ((unsigned)(gx+k) < W) {
                        if (IS_PRED) { float x = pred[gy*W + gx + k]; *vk = 1.f/(1.f+__expf(-x)); }
                        else         { *vk = (float)targ[gy*W + gx + k]; }
                    }
                }
            }
        }
        st4(&s0[r*SW + c4], v);
    }
    __syncthreads();

    for (int i = tid; i < 18*18; i += NT) {
        int r = 1 + i / 18, c4 = (i % 18) * 4;
        int o = r*SW + c4;
        float4 e = cross_min(ld4(&s0[o-SW]), ld4(&s0[o]), ld4(&s0[o+SW]),
                             s0[o-1], s0[o+4]);
        if (BORDER) mask_oob(e, y0-2+r, x0-4+c4, NINF);
        st4(&s1[o], e);
    }
    __syncthreads();

    {
        int r  = 2 + (tid >> 4);
        int c4 = ((tid & 15) + 1) * 4;
        int o  = r*SW + c4;
        float4 d = dil3x3(s1, o);
        float4 base = ld4(&s0[o]);
        float4 sk;
        sk.x = fmaxf(base.x - d.x, 0.f);
        sk.y = fmaxf(base.y - d.y, 0.f);
        sk.z = fmaxf(base.z - d.z, 0.f);
        sk.w = fmaxf(base.w - d.w, 0.f);
        size_t idx = (size_t)(y0 + r - 2) * W + (x0 + c4 - 4);
        st4(&baseOut[idx], base);
        st4(&skelOut[idx], sk);
    }
}

template<bool IS_PRED>
__global__ __launch_bounds__(NT)
void init_kernel(const float* __restrict__ pred, const int* __restrict__ targ,
                 float* __restrict__ baseOut, float* __restrict__ skelOut)
{
    __shared__ float s0[SHN*SW];
    __shared__ float s1[SHN*SW];
    int x0 = blockIdx.x * TW, y0 = blockIdx.y * TH;
    size_t off = (size_t)blockIdx.z * H * W;
    int tid = threadIdx.x;
    const float* p = IS_PRED ? pred + off : nullptr;
    const int*   t = IS_PRED ? nullptr : targ + off;
    bool border = (blockIdx.x == 0) | (blockIdx.x == gridDim.x-1) |
                  (blockIdx.y == 0) | (blockIdx.y == gridDim.y-1);
    if (border) init_impl<IS_PRED, true >(p, t, baseOut+off, skelOut+off, x0, y0, s0, s1, tid);
    else        init_impl<IS_PRED, false>(p, t, baseOut+off, skelOut+off, x0, y0, s0, s1, tid);
}

// ---------------------------------------------------------------------------
// Reduction: 7 sums over 8M elements
// ---------------------------------------------------------------------------
#define RED_BLOCKS 2048
#define RED_THREADS 256

__global__ __launch_bounds__(RED_THREADS)
void reduce_kernel(const int* __restrict__ targ)
{
    const int NV = NTOT / 4;
    const float4* p4   = (const float4*)g_prob;
    const float4* sp4  = (const float4*)g_skelP;
    const float4* st4p = (const float4*)g_skelT;
    const int4*   t4   = (const int4*)targ;

    float a0=0.f, a1=0.f, a2=0.f, a3=0.f, a4=0.f, a5=0.f, a6=0.f;

    for (int v = blockIdx.x * RED_THREADS + threadIdx.x; v < NV;
         v += gridDim.x * RED_THREADS) {
        float4 p  = p4[v];
        float4 sp = sp4[v];
        float4 st = st4p[v];
        int4   ti = t4[v];
        float tx = (float)ti.x, ty = (float)ti.y, tz = (float)ti.z, tw = (float)ti.w;

        a0 += sp.x*tx + sp.y*ty + sp.z*tz + sp.w*tw;
        a1 += sp.x + sp.y + sp.z + sp.w;
        a2 += st.x*p.x + st.y*p.y + st.z*p.z + st.w*p.w;
        a3 += st.x + st.y + st.z + st.w;
        a4 += p.x*tx + p.y*ty + p.z*tz + p.w*tw;
        a5 += p.x + p.y + p.z + p.w;
        a6 += tx + ty + tz + tw;
    }

    #pragma unroll
    for (int off = 16; off > 0; off >>= 1) {
        a0 += __shfl_down_sync(0xFFFFFFFF, a0, off);
        a1 += __shfl_down_sync(0xFFFFFFFF, a1, off);
        a2 += __shfl_down_sync(0xFFFFFFFF, a2, off);
        a3 += __shfl_down_sync(0xFFFFFFFF, a3, off);
        a4 += __shfl_down_sync(0xFFFFFFFF, a4, off);
        a5 += __shfl_down_sync(0xFFFFFFFF, a5, off);
        a6 += __shfl_down_sync(0xFFFFFFFF, a6, off);
    }

    __shared__ double sacc[7][RED_THREADS/32];
    int warp = threadIdx.x >> 5, lane = threadIdx.x & 31;
    if (lane == 0) {
        sacc[0][warp]=a0; sacc[1][warp]=a1; sacc[2][warp]=a2;
        sacc[3][warp]=a3; sacc[4][warp]=a4; sacc[5][warp]=a5; sacc[6][warp]=a6;
    }
    __syncthreads();
    if (threadIdx.x < 7) {
        double s = 0.0;
        #pragma unroll
        for (int wv = 0; wv < RED_THREADS/32; wv++) s += sacc[threadIdx.x][wv];
        atomicAdd(&g_sums[threadIdx.x], s);
    }
}

__global__ void finalize_kernel(float* __restrict__ out)
{
    double S_spt=g_sums[0], S_sp=g_sums[1], S_stp=g_sums[2], S_st=g_sums[3];
    double S_pt =g_sums[4], S_p =g_sums[5], S_t =g_sums[6];
    const double SMOOTH = 1.0;
    double tprec = (S_spt + SMOOTH) / (S_sp + SMOOTH);
    double tsens = (S_stp + SMOOTH) / (S_st + SMOOTH);
    double cl    = 2.0 * tprec * tsens / (tprec + tsens + 1e-7);
    double dice  = (2.0 * S_pt + SMOOTH) / (S_p + S_t + SMOOTH);
    out[0] = (float)(1.0 - (0.5 * dice + 0.5 * cl));
}

// ---------------------------------------------------------------------------
// Launch
// ---------------------------------------------------------------------------
extern "C" void kernel_launch(void* const* d_in, const int* in_sizes, int n_in,
                              void* d_out, int out_size)
{
    const float* pred = (const float*)d_in[0];
    const int*   targ = (const int*)d_in[1];
    float* out = (float*)d_out;

    float *prob, *skelP, *skelT, *bufA, *bufB;
    cudaGetSymbolAddress((void**)&prob,  g_prob);
    cudaGetSymbolAddress((void**)&skelP, g_skelP);
    cudaGetSymbolAddress((void**)&skelT, g_skelT);
    cudaGetSymbolAddress((void**)&bufA,  g_bufA);
    cudaGetSymbolAddress((void**)&bufB,  g_bufB);

    dim3 grd(W / TW, H / TH, B);   // 16 x 64 x 8

    zero_sums<<<1, 32>>>();

    // ---- pred skeleton: init + 5 fused double-iterations ----
    init_kernel<true><<<grd, NT>>>(pred, nullptr, prob, skelP);
    {
        const float* in = prob;
        float* ob = bufB;
        for (int i = 0; i < 5; i++) {
            if (i < 4) iter2_kernel<true ><<<grd, NT>>>(in, ob, skelP);
            else       iter2_kernel<false><<<grd, NT>>>(in, ob, skelP);
            in = ob;
            ob = (ob == bufB) ? bufA : bufB;
        }
    }

    // ---- target skeleton ----
    init_kernel<false><<<grd, NT>>>(nullptr, targ, bufA, skelT);
    {
        const float* in = bufA;
        float* ob = bufB;
        for (int i = 0; i < 5; i++) {
            if (i < 4) iter2_kernel<true ><<<grd, NT>>>(in, ob, skelT);
            else       iter2_kernel<false><<<grd, NT>>>(in, ob, skelT);
            in = ob;
            ob = (ob == bufB) ? bufA : bufB;
        }
    }

    reduce_kernel<<<RED_BLOCKS, RED_THREADS>>>(targ);
    finalize_kernel<<<1, 1>>>(out);
}